// round 13
// baseline (speedup 1.0000x reference)
#include <cuda_runtime.h>
#include <math.h>
#include <cstdint>

#define DIM   2048
#define NH    16
#define HD    128
#define HD2   256
#define ROPE  64
#define BB    2
#define SS    2048
#define MS    (BB*SS)        // 4096 rows
#define INNER (2*NH*HD)      // 4096
#define LAMBDA_INIT 0.7836057665316244f
#define EPSV  1e-5f
#define SCALE 0.088388347648318447f   // HD^-0.5

// ---------------- scratch ------------------------------------------------------
__device__ float d_Q[(size_t)MS*INNER];
__device__ float d_K[(size_t)MS*INNER];
__device__ float d_V[(size_t)MS*INNER];
__device__ float d_O[(size_t)MS*INNER];
// tf32 pre-rounded GEMM inputs (rounded once instead of at every fragment load)
__device__ float d_Xr [(size_t)MS*DIM];
__device__ float d_Wqr[(size_t)INNER*DIM];
__device__ float d_Wkr[(size_t)INNER*DIM];
__device__ float d_Wvr[(size_t)INNER*DIM];
__device__ float d_Wor[(size_t)DIM*INNER];

// ---------------- helpers ------------------------------------------------------
__device__ __forceinline__ uint32_t f2tf(float f) {
    uint32_t u;
    asm("cvt.rna.tf32.f32 %0, %1;" : "=r"(u) : "f"(f));
    return u;
}
__device__ __forceinline__ float rtf32f(float f) {
    return __uint_as_float(f2tf(f));
}
__device__ __forceinline__ uint32_t cvta_smem(const void* p) {
    uint32_t a;
    asm("{ .reg .u64 t; cvta.to.shared.u64 t, %1; cvt.u32.u64 %0, t; }" : "=r"(a) : "l"(p));
    return a;
}
#define FU(x) __float_as_uint(x)
#define MMA4(c, a0,a1,a2,a3, b0,b1) \
  asm volatile("mma.sync.aligned.m16n8k8.row.col.f32.tf32.tf32.f32 " \
      "{%0,%1,%2,%3}, {%4,%5,%6,%7}, {%8,%9}, {%0,%1,%2,%3};" \
      : "+f"((c)[0]), "+f"((c)[1]), "+f"((c)[2]), "+f"((c)[3]) \
      : "r"(a0), "r"(a1), "r"(a2), "r"(a3), "r"(b0), "r"(b1))

// ---------------- tf32 pre-rounding pass ----------------------------------------
__global__ void round_tf32_kernel(const float4* __restrict__ in, float4* __restrict__ out, int n4)
{
    int i = blockIdx.x * blockDim.x + threadIdx.x;
    if (i >= n4) return;
    float4 v = in[i];
    v.x = rtf32f(v.x); v.y = rtf32f(v.y); v.z = rtf32f(v.z); v.w = rtf32f(v.w);
    out[i] = v;
}

// ---------------- tf32 mma.sync GEMM NT: C[M,N] = A[M,K] * B[N,K]^T ------------
// 3-stage cp.async pipeline, pitch 36. Inputs pre-rounded to tf32 -> hot loop is
// pure LDS.128 + mma (float4 k-relabeled fragments, conflict-free per phase).
// mode: 0 = plain fp32 out; 1 = round to tf32; 2 = K-RoPE then round.
#define BM 128
#define BN 128
#define BK 32
#define PITCH 36
#define STG (BM*PITCH)
#define GEMM_SMEM (6*STG*(int)sizeof(float))   // 110592 B, 2 CTAs/SM

__global__ __launch_bounds__(256, 2) void gemm_mma(
    const float* __restrict__ A, const float* __restrict__ B, float* __restrict__ C,
    int M, int N, int K, int mode,
    const float* __restrict__ fcos, const float* __restrict__ fsin)
{
    extern __shared__ float sm[];
    float* As = sm;            // [3][128][36]
    float* Bs = sm + 3*STG;    // [3][128][36]

    const int tid  = threadIdx.x;
    const int wid  = tid >> 5;
    const int lane = tid & 31;
    const int wm   = wid & 3;
    const int wn   = wid >> 2;
    const int g    = lane >> 2;
    const int t4   = lane & 3;
    const int m0 = blockIdx.y * BM;
    const int n0 = blockIdx.x * BN;
    const int nk = K / BK;

    float c[2][8][4];
#pragma unroll
    for (int t = 0; t < 2; t++)
#pragma unroll
        for (int n = 0; n < 8; n++)
#pragma unroll
            for (int j = 0; j < 4; j++) c[t][n][j] = 0.f;

    const uint32_t asb = cvta_smem(As);
    const uint32_t bsb = cvta_smem(Bs);

#define LOAD_STAGE(s, kb) do { \
    _Pragma("unroll") \
    for (int it = 0; it < 4; it++) { \
        int ch = tid + it * 256; \
        int row = ch >> 3, q = ch & 7; \
        const float* srcA = A + (size_t)(m0 + row) * K + (kb) + q * 4; \
        uint32_t dstA = asb + ((s) * STG + row * PITCH + q * 4) * 4; \
        asm volatile("cp.async.cg.shared.global [%0], [%1], 16;" :: "r"(dstA), "l"(srcA)); \
        const float* srcB = B + (size_t)(n0 + row) * K + (kb) + q * 4; \
        uint32_t dstB = bsb + ((s) * STG + row * PITCH + q * 4) * 4; \
        asm volatile("cp.async.cg.shared.global [%0], [%1], 16;" :: "r"(dstB), "l"(srcB)); \
    } \
    asm volatile("cp.async.commit_group;"); \
} while (0)

    LOAD_STAGE(0, 0);
    LOAD_STAGE(1, BK);

    for (int i = 0; i < nk; i++) {
        const int s = i % 3;
        if (i + 2 < nk) {
            LOAD_STAGE((i + 2) % 3, (i + 2) * BK);
            asm volatile("cp.async.wait_group 2;");
        } else if (i + 1 < nk) {
            asm volatile("cp.async.wait_group 1;");
        } else {
            asm volatile("cp.async.wait_group 0;");
        }
        __syncthreads();

        const float* Abase = As + s * STG + (wm * 32 + g) * PITCH + 4 * t4;
        const float* Bbase = Bs + s * STG + (wn * 64 + g) * PITCH + 4 * t4;
#pragma unroll
        for (int grp = 0; grp < 2; grp++) {
            float4 a00 = *(const float4*)(Abase + grp * 16);
            float4 a01 = *(const float4*)(Abase + 8 * PITCH + grp * 16);
            float4 a10 = *(const float4*)(Abase + 16 * PITCH + grp * 16);
            float4 a11 = *(const float4*)(Abase + 24 * PITCH + grp * 16);
#pragma unroll
            for (int n = 0; n < 8; n++) {
                float4 bv = *(const float4*)(Bbase + n * 8 * PITCH + grp * 16);
                MMA4(c[0][n], FU(a00.x), FU(a01.x), FU(a00.y), FU(a01.y), FU(bv.x), FU(bv.y));
                MMA4(c[0][n], FU(a00.z), FU(a01.z), FU(a00.w), FU(a01.w), FU(bv.z), FU(bv.w));
                MMA4(c[1][n], FU(a10.x), FU(a11.x), FU(a10.y), FU(a11.y), FU(bv.x), FU(bv.y));
                MMA4(c[1][n], FU(a10.z), FU(a11.z), FU(a10.w), FU(a11.w), FU(bv.z), FU(bv.w));
            }
        }
        __syncthreads();
    }

    // epilogue: optional fused K-RoPE (mode 2) + tf32 rounding (mode >= 1)
#pragma unroll
    for (int t = 0; t < 2; t++) {
        const int row = m0 + wm * 32 + t * 16 + g;
#pragma unroll
        for (int n = 0; n < 8; n++) {
            const int col = n0 + wn * 64 + n * 8 + t4 * 2;
            float v0 = c[t][n][0], v1 = c[t][n][1];
            float v2 = c[t][n][2], v3 = c[t][n][3];
            if (mode == 2) {
                int ch = col & 127;
                if (ch < ROPE) {
                    int p = ch >> 1;
                    int s0 = row & (SS-1), s1 = (row + 8) & (SS-1);
                    float c0 = fcos[s0*32 + p], sn0 = fsin[s0*32 + p];
                    float c1 = fcos[s1*32 + p], sn1 = fsin[s1*32 + p];
                    float r0 = v0*c0 - v1*sn0, i0 = v0*sn0 + v1*c0;
                    float r1 = v2*c1 - v3*sn1, i1 = v2*sn1 + v3*c1;
                    v0 = r0; v1 = i0; v2 = r1; v3 = i1;
                }
            }
            if (mode >= 1) {
                v0 = rtf32f(v0); v1 = rtf32f(v1);
                v2 = rtf32f(v2); v3 = rtf32f(v3);
            }
            *(float2*)&C[(size_t)row * N + col]       = make_float2(v0, v1);
            *(float2*)&C[(size_t)(row + 8) * N + col] = make_float2(v2, v3);
        }
    }
}

// ---------------- tensor-core differential flash attention ---------------------
// (R9/R10 measured-best version, unchanged)
#define QKP 272
#define VP  264
#define PP  36
#define SM_KS (64*QKP)
#define SM_VS (SM_KS + 64*QKP)
#define SM_PS (SM_VS + 64*VP)
#define SM_MS (SM_PS + 2*64*PP)
#define ATT_SMEM ((SM_MS + 3*128 + 4) * (int)sizeof(float))   // 226832 B

__global__ __launch_bounds__(512) void attn_mma(
    const float* __restrict__ rms_scale,
    const float* __restrict__ fcos, const float* __restrict__ fsin,
    const float* __restrict__ lq1, const float* __restrict__ lk1,
    const float* __restrict__ lq2, const float* __restrict__ lk2)
{
    extern __shared__ float smf[];
    float* Qs = smf;              // [64][272]
    float* Ks = smf + SM_KS;      // [2][32][272]
    float* Vs = smf + SM_VS;      // [2][32][264]
    float* Ps = smf + SM_PS;      // [2][64][36]
    float* ms = smf + SM_MS;
    float* ls = ms + 128;
    float* fs = ls + 128;
    float* lam_s = fs + 128;
    float* Osm = Ks;              // epilogue reuse: [64][272]

    const int qt   = 31 - blockIdx.x;
    const int bh   = blockIdx.y;
    const int b    = bh >> 4, h = bh & 15;
    const int tid  = threadIdx.x;
    const int wid  = tid >> 5;
    const int lane = tid & 31;
    const int g    = lane >> 2;
    const int t4   = lane & 3;
    const int qb   = qt * 64;

    const int s_qrg = wid & 3, s_br = (wid >> 2) & 1, s_kh = wid >> 3;
    const int p_vq = wid & 3, p_br = (wid >> 2) & 1, p_qrg = wid >> 3;

    const uint32_t ks_u = cvta_smem(Ks);
    const uint32_t vs_u = cvta_smem(Vs);

    const size_t qgbase = (size_t)(b*SS + qb) * INNER + h*HD2;
    const int nkt = 2*qt + 2;

#define ATT_PREFETCH(stg, kt_) do { \
    const size_t kb_ = (size_t)(b*SS + (kt_)*32) * INNER + h*HD2; \
    _Pragma("unroll") \
    for (int it = 0; it < 4; it++) { \
        int idx_ = tid + it*512; \
        int r_ = idx_ >> 6, c4_ = (idx_ & 63) << 2; \
        uint32_t offk = (uint32_t)(((stg)*32 + r_)*QKP + c4_) * 4; \
        uint32_t offv = (uint32_t)(((stg)*32 + r_)*VP + c4_) * 4; \
        asm volatile("cp.async.cg.shared.global [%0], [%1], 16;" \
                     :: "r"(ks_u + offk), "l"(&d_K[kb_ + (size_t)r_*INNER + c4_])); \
        asm volatile("cp.async.cg.shared.global [%0], [%1], 16;" \
                     :: "r"(vs_u + offv), "l"(&d_V[kb_ + (size_t)r_*INNER + c4_])); \
    } \
    asm volatile("cp.async.commit_group;"); \
} while (0)

    ATT_PREFETCH(0, 0);

    // Q tile load (64 x 256)
#pragma unroll
    for (int it = 0; it < 8; it++) {
        int idx = tid + it*512;
        int r = idx >> 6, c4 = (idx & 63) << 2;
        *(float4*)&Qs[r*QKP + c4] = *(const float4*)&d_Q[qgbase + (size_t)r*INNER + c4];
    }
    if (tid < 128) { ms[tid] = -1e30f; ls[tid] = 0.f; }
    if (wid == 0) {
        float s1 = 0.f, s2 = 0.f;
#pragma unroll
        for (int i = 0; i < 4; i++) {
            int idx = h*HD + lane*4 + i;
            s1 += lq1[idx]*lk1[idx];
            s2 += lq2[idx]*lk2[idx];
        }
#pragma unroll
        for (int o = 16; o; o >>= 1) {
            s1 += __shfl_xor_sync(0xffffffffu, s1, o);
            s2 += __shfl_xor_sync(0xffffffffu, s2, o);
        }
        if (lane == 0) lam_s[0] = __expf(s1) - __expf(s2) + LAMBDA_INIT;
    }
    __syncthreads();

    // fused RoPE on Q (rounded to tf32): dims 0..63 of each 128-half
#pragma unroll
    for (int it = 0; it < 8; it++) {
        int idx = tid + it*512;
        int r = idx >> 6, pp = idx & 63;
        int half = pp >> 5, p = pp & 31;
        float c  = fcos[(qb + r)*32 + p];
        float sn = fsin[(qb + r)*32 + p];
        float* x = &Qs[r*QKP + half*128 + 2*p];
        float xr = x[0], xi = x[1];
        x[0] = rtf32f(xr*c - xi*sn);
        x[1] = rtf32f(xr*sn + xi*c);
    }

    float oc[2][8][4];
#pragma unroll
    for (int t = 0; t < 2; t++)
#pragma unroll
        for (int n = 0; n < 8; n++)
#pragma unroll
            for (int j = 0; j < 4; j++) oc[t][n][j] = 0.f;

    for (int kt = 0; kt < nkt; kt++) {
        const int st = kt & 1;
        if (kt + 1 < nkt) {
            ATT_PREFETCH(st ^ 1, kt + 1);
            asm volatile("cp.async.wait_group 1;");
        } else {
            asm volatile("cp.async.wait_group 0;");
        }
        __syncthreads();

        // ---- scores: float4 frags, k-relabeled ----
        {
            float cs[2][4] = {{0,0,0,0},{0,0,0,0}};
            const float* Qb = Qs + (s_qrg*16 + g)*QKP + s_br*128 + 4*t4;
            const float* Kb = Ks + st*32*QKP + (s_kh*16 + g)*QKP + s_br*128 + 4*t4;
#pragma unroll
            for (int grp = 0; grp < 8; grp++) {
                float4 qa  = *(const float4*)(Qb + grp*16);
                float4 qb_ = *(const float4*)(Qb + 8*QKP + grp*16);
                float4 ka  = *(const float4*)(Kb + grp*16);
                float4 kb2 = *(const float4*)(Kb + 8*QKP + grp*16);
                MMA4(cs[0], FU(qa.x), FU(qb_.x), FU(qa.y), FU(qb_.y), FU(ka.x),  FU(ka.y));
                MMA4(cs[0], FU(qa.z), FU(qb_.z), FU(qa.w), FU(qb_.w), FU(ka.z),  FU(ka.w));
                MMA4(cs[1], FU(qa.x), FU(qb_.x), FU(qa.y), FU(qb_.y), FU(kb2.x), FU(kb2.y));
                MMA4(cs[1], FU(qa.z), FU(qb_.z), FU(qa.w), FU(qb_.w), FU(kb2.z), FU(kb2.w));
            }
            const int row0 = qb + s_qrg*16 + g;
#pragma unroll
            for (int nt = 0; nt < 2; nt++) {
                int coln = kt*32 + s_kh*16 + nt*8 + 2*t4;
                float* pp = Ps + (s_br*64 + s_qrg*16 + g)*PP + s_kh*16 + nt*8 + 2*t4;
                pp[0]      = (coln   <= row0)   ? cs[nt][0]*SCALE : -1e30f;
                pp[1]      = (coln+1 <= row0)   ? cs[nt][1]*SCALE : -1e30f;
                pp[8*PP]   = (coln   <= row0+8) ? cs[nt][2]*SCALE : -1e30f;
                pp[8*PP+1] = (coln+1 <= row0+8) ? cs[nt][3]*SCALE : -1e30f;
            }
        }
        __syncthreads();

        // ---- online softmax (each warp: 8 row-branches), P rounded to tf32 ----
#pragma unroll
        for (int j = 0; j < 8; j++) {
            int rb = wid*8 + j;
            int br = rb >> 6, row = rb & 63;
            float* pr = Ps + (br*64 + row)*PP;
            float v = pr[lane];
            float mx = v;
#pragma unroll
            for (int o = 16; o; o >>= 1) mx = fmaxf(mx, __shfl_xor_sync(0xffffffffu, mx, o));
            float mo = ms[br*64 + row];
            float mn = fmaxf(mo, mx);
            float p = (v > -1e29f) ? rtf32f(__expf(v - mn)) : 0.f;
            float su = p;
#pragma unroll
            for (int o = 16; o; o >>= 1) su += __shfl_xor_sync(0xffffffffu, su, o);
            pr[lane] = p;
            if (lane == 0) {
                float f = __expf(mo - mn);
                fs[br*64 + row] = f;
                ls[br*64 + row] = ls[br*64 + row]*f + su;
                ms[br*64 + row] = mn;
            }
        }
        __syncthreads();

        // ---- PV: O_br += P_br V (warp: 32q x 64v, kdim 32) ----
        {
            const int rbase = p_br*64 + p_qrg*32;
            float f0 = fs[rbase + g],       f1 = fs[rbase + g + 8];
            float f2_ = fs[rbase + 16 + g], f3_ = fs[rbase + 16 + g + 8];
#pragma unroll
            for (int nt = 0; nt < 8; nt++) {
                oc[0][nt][0] *= f0;  oc[0][nt][1] *= f0;
                oc[0][nt][2] *= f1;  oc[0][nt][3] *= f1;
                oc[1][nt][0] *= f2_; oc[1][nt][1] *= f2_;
                oc[1][nt][2] *= f3_; oc[1][nt][3] *= f3_;
            }
            const float* Pb = Ps + (p_br*64 + p_qrg*32 + g)*PP;
            const float* Vb = Vs + st*32*VP + p_vq*64;
#pragma unroll
            for (int ki = 0; ki < 4; ki++) {
                const int kc = ki*8 + t4;
                uint32_t pa[2][4];
#pragma unroll
                for (int t = 0; t < 2; t++) {
                    const float* pr = Pb + t*16*PP;
                    pa[t][0] = FU(pr[kc]);
                    pa[t][1] = FU(pr[8*PP + kc]);
                    pa[t][2] = FU(pr[kc+4]);
                    pa[t][3] = FU(pr[8*PP + kc+4]);
                }
                const float* v0p = Vb + kc*VP + g;
                const float* v1p = v0p + 4*VP;
#pragma unroll
                for (int nt = 0; nt < 8; nt++) {
                    uint32_t b0 = FU(v0p[nt*8]);
                    uint32_t b1 = FU(v1p[nt*8]);
                    MMA4(oc[0][nt], pa[0][0], pa[0][1], pa[0][2], pa[0][3], b0, b1);
                    MMA4(oc[1][nt], pa[1][0], pa[1][1], pa[1][2], pa[1][3], b0, b1);
                }
            }
        }
        __syncthreads();
    }

    // ---- epilogue: combine branches, RMS-norm, write d_O ----
    {
        const int rbase = p_qrg*32;
        const int lb = p_br*64 + rbase;
        float li0 = 1.f / ls[lb + g];
        float li1 = 1.f / ls[lb + g + 8];
        float li2 = 1.f / ls[lb + 16 + g];
        float li3 = 1.f / ls[lb + 16 + g + 8];

        if (p_br == 0) {
#pragma unroll
            for (int t = 0; t < 2; t++) {
                int r0 = rbase + t*16 + g;
                float la = t ? li2 : li0, lbv = t ? li3 : li1;
#pragma unroll
                for (int nt = 0; nt < 8; nt++) {
                    int col = p_vq*64 + nt*8 + 2*t4;
                    Osm[r0*QKP + col]       = oc[t][nt][0]*la;
                    Osm[r0*QKP + col + 1]   = oc[t][nt][1]*la;
                    Osm[(r0+8)*QKP + col]   = oc[t][nt][2]*lbv;
                    Osm[(r0+8)*QKP + col+1] = oc[t][nt][3]*lbv;
                }
            }
        }
        __syncthreads();
        if (p_br == 1) {
            const float lam = lam_s[0];
#pragma unroll
            for (int t = 0; t < 2; t++) {
                int r0 = rbase + t*16 + g;
                float la = t ? li2 : li0, lbv = t ? li3 : li1;
#pragma unroll
                for (int nt = 0; nt < 8; nt++) {
                    int col = p_vq*64 + nt*8 + 2*t4;
                    Osm[r0*QKP + col]       -= lam*oc[t][nt][0]*la;
                    Osm[r0*QKP + col + 1]   -= lam*oc[t][nt][1]*la;
                    Osm[(r0+8)*QKP + col]   -= lam*oc[t][nt][2]*lbv;
                    Osm[(r0+8)*QKP + col+1] -= lam*oc[t][nt][3]*lbv;
                }
            }
        }
        __syncthreads();

#pragma unroll
        for (int j = 0; j < 4; j++) {
            int row = wid*4 + j;
            float vals[8];
            float ssq = 0.f;
#pragma unroll
            for (int i = 0; i < 8; i++) {
                float v = Osm[row*QKP + lane + 32*i];
                vals[i] = v;
                ssq += v*v;
            }
#pragma unroll
            for (int o = 16; o; o >>= 1) ssq += __shfl_xor_sync(0xffffffffu, ssq, o);
            float rn = rsqrtf(ssq * (1.f/256.f) + EPSV) * (1.f - LAMBDA_INIT);
            size_t gb = (size_t)(b*SS + qb + row) * INNER + h*HD2;
#pragma unroll
            for (int i = 0; i < 8; i++) {
                int col = lane + 32*i;
                d_O[gb + col] = vals[i] * rn * rms_scale[h*HD2 + col];
            }
        }
    }
}

// ---------------- launch --------------------------------------------------------
extern "C" void kernel_launch(void* const* d_in, const int* in_sizes, int n_in,
                              void* d_out, int out_size)
{
    const float* x    = (const float*)d_in[0];
    const float* w_q  = (const float*)d_in[1];
    const float* w_k  = (const float*)d_in[2];
    const float* w_v  = (const float*)d_in[3];
    const float* w_o  = (const float*)d_in[4];
    const float* lq1  = (const float*)d_in[5];
    const float* lk1  = (const float*)d_in[6];
    const float* lq2  = (const float*)d_in[7];
    const float* lk2  = (const float*)d_in[8];
    const float* rsc  = (const float*)d_in[9];
    const float* fcos = (const float*)d_in[10];
    const float* fsin = (const float*)d_in[11];
    float* out = (float*)d_out;

    float *Q, *K, *V, *O, *Xr, *Wqr, *Wkr, *Wvr, *Wor;
    cudaGetSymbolAddress((void**)&Q,   d_Q);
    cudaGetSymbolAddress((void**)&K,   d_K);
    cudaGetSymbolAddress((void**)&V,   d_V);
    cudaGetSymbolAddress((void**)&O,   d_O);
    cudaGetSymbolAddress((void**)&Xr,  d_Xr);
    cudaGetSymbolAddress((void**)&Wqr, d_Wqr);
    cudaGetSymbolAddress((void**)&Wkr, d_Wkr);
    cudaGetSymbolAddress((void**)&Wvr, d_Wvr);
    cudaGetSymbolAddress((void**)&Wor, d_Wor);

    cudaFuncSetAttribute(gemm_mma, cudaFuncAttributeMaxDynamicSharedMemorySize, GEMM_SMEM);
    cudaFuncSetAttribute(attn_mma, cudaFuncAttributeMaxDynamicSharedMemorySize, ATT_SMEM);

    const int n4 = (MS * DIM) / 4;   // 2M float4 per 4096x2048 matrix
    round_tf32_kernel<<<n4/256, 256>>>((const float4*)x,   (float4*)Xr,  n4);  // idx 0
    round_tf32_kernel<<<n4/256, 256>>>((const float4*)w_q, (float4*)Wqr, n4);  // idx 1
    round_tf32_kernel<<<n4/256, 256>>>((const float4*)w_k, (float4*)Wkr, n4);  // idx 2

    dim3 gq(INNER/BN, MS/BM);
    gemm_mma<<<gq, 256, GEMM_SMEM>>>(Xr, Wqr, Q, MS, INNER, DIM, 1, nullptr, nullptr); // idx 3 (profiled)
    gemm_mma<<<gq, 256, GEMM_SMEM>>>(Xr, Wkr, K, MS, INNER, DIM, 2, fcos, fsin);       // idx 4: +RoPE

    round_tf32_kernel<<<n4/256, 256>>>((const float4*)w_v, (float4*)Wvr, n4);          // idx 5
    gemm_mma<<<gq, 256, GEMM_SMEM>>>(Xr, Wvr, V, MS, INNER, DIM, 1, nullptr, nullptr); // idx 6
    round_tf32_kernel<<<n4/256, 256>>>((const float4*)w_o, (float4*)Wor, n4);          // idx 7

    attn_mma<<<dim3(SS/64, BB*NH), 512, ATT_SMEM>>>(rsc, fcos, fsin, lq1, lk1, lq2, lk2); // idx 8

    dim3 go(DIM/BN, MS/BM);
    gemm_mma<<<go, 256, GEMM_SMEM>>>(O, Wor, out, MS, DIM, INNER, 0, nullptr, nullptr);   // idx 9
}

// round 17
// speedup vs baseline: 1.1864x; 1.1864x over previous
#include <cuda_runtime.h>
#include <math.h>
#include <cstdint>

#define DIM   2048
#define NH    16
#define HD    128
#define HD2   256
#define ROPE  64
#define BB    2
#define SS    2048
#define MS    (BB*SS)        // 4096 rows
#define INNER (2*NH*HD)      // 4096
#define LAMBDA_INIT 0.7836057665316244f
#define EPSV  1e-5f
#define SCALE 0.088388347648318447f   // HD^-0.5

// ---------------- scratch ------------------------------------------------------
__device__ float d_Q[(size_t)MS*INNER];
__device__ float d_K[(size_t)MS*INNER];
__device__ float d_V[(size_t)MS*INNER];
__device__ float d_O[(size_t)MS*INNER];
// tf32 pre-rounded GEMM inputs (rounded once instead of at every fragment load)
__device__ float d_Xr [(size_t)MS*DIM];
__device__ float d_Wqr[(size_t)INNER*DIM];
__device__ float d_Wkr[(size_t)INNER*DIM];
__device__ float d_Wvr[(size_t)INNER*DIM];
__device__ float d_Wor[(size_t)DIM*INNER];

// ---------------- helpers ------------------------------------------------------
__device__ __forceinline__ uint32_t f2tf(float f) {
    uint32_t u;
    asm("cvt.rna.tf32.f32 %0, %1;" : "=r"(u) : "f"(f));
    return u;
}
__device__ __forceinline__ float rtf32f(float f) {
    return __uint_as_float(f2tf(f));
}
__device__ __forceinline__ uint32_t cvta_smem(const void* p) {
    uint32_t a;
    asm("{ .reg .u64 t; cvta.to.shared.u64 t, %1; cvt.u32.u64 %0, t; }" : "=r"(a) : "l"(p));
    return a;
}
#define FU(x) __float_as_uint(x)
#define MMA4(c, a0,a1,a2,a3, b0,b1) \
  asm volatile("mma.sync.aligned.m16n8k8.row.col.f32.tf32.tf32.f32 " \
      "{%0,%1,%2,%3}, {%4,%5,%6,%7}, {%8,%9}, {%0,%1,%2,%3};" \
      : "+f"((c)[0]), "+f"((c)[1]), "+f"((c)[2]), "+f"((c)[3]) \
      : "r"(a0), "r"(a1), "r"(a2), "r"(a3), "r"(b0), "r"(b1))

// ---------------- tf32 pre-rounding pass ----------------------------------------
__global__ void round_tf32_kernel(const float4* __restrict__ in, float4* __restrict__ out, int n4)
{
    int i = blockIdx.x * blockDim.x + threadIdx.x;
    if (i >= n4) return;
    float4 v = in[i];
    v.x = rtf32f(v.x); v.y = rtf32f(v.y); v.z = rtf32f(v.z); v.w = rtf32f(v.w);
    out[i] = v;
}

// ---------------- tf32 mma.sync GEMM NT: C[M,N] = A[M,K] * B[N,K]^T ------------
// R10 structure (3-stage cp.async, pitch 36, conflict-free SCALAR frag loads),
// but inputs pre-rounded to tf32 in global -> zero cvt in the hot loop.
// mode: 0 = plain fp32 out; 1 = round to tf32; 2 = K-RoPE then round.
#define BM 128
#define BN 128
#define BK 32
#define PITCH 36
#define STG (BM*PITCH)
#define GEMM_SMEM (6*STG*(int)sizeof(float))   // 110592 B, 2 CTAs/SM

__global__ __launch_bounds__(256, 2) void gemm_mma(
    const float* __restrict__ A, const float* __restrict__ B, float* __restrict__ C,
    int M, int N, int K, int mode,
    const float* __restrict__ fcos, const float* __restrict__ fsin)
{
    extern __shared__ float sm[];
    float* As = sm;            // [3][128][36]
    float* Bs = sm + 3*STG;    // [3][128][36]

    const int tid  = threadIdx.x;
    const int wid  = tid >> 5;
    const int lane = tid & 31;
    const int wm   = wid & 3;
    const int wn   = wid >> 2;
    const int g    = lane >> 2;
    const int t4   = lane & 3;
    const int m0 = blockIdx.y * BM;
    const int n0 = blockIdx.x * BN;
    const int nk = K / BK;

    float c[2][8][4];
#pragma unroll
    for (int t = 0; t < 2; t++)
#pragma unroll
        for (int n = 0; n < 8; n++)
#pragma unroll
            for (int j = 0; j < 4; j++) c[t][n][j] = 0.f;

    const uint32_t asb = cvta_smem(As);
    const uint32_t bsb = cvta_smem(Bs);

#define LOAD_STAGE(s, kb) do { \
    _Pragma("unroll") \
    for (int it = 0; it < 4; it++) { \
        int ch = tid + it * 256; \
        int row = ch >> 3, q = ch & 7; \
        const float* srcA = A + (size_t)(m0 + row) * K + (kb) + q * 4; \
        uint32_t dstA = asb + ((s) * STG + row * PITCH + q * 4) * 4; \
        asm volatile("cp.async.cg.shared.global [%0], [%1], 16;" :: "r"(dstA), "l"(srcA)); \
        const float* srcB = B + (size_t)(n0 + row) * K + (kb) + q * 4; \
        uint32_t dstB = bsb + ((s) * STG + row * PITCH + q * 4) * 4; \
        asm volatile("cp.async.cg.shared.global [%0], [%1], 16;" :: "r"(dstB), "l"(srcB)); \
    } \
    asm volatile("cp.async.commit_group;"); \
} while (0)

    LOAD_STAGE(0, 0);
    LOAD_STAGE(1, BK);

    for (int i = 0; i < nk; i++) {
        const int s = i % 3;
        if (i + 2 < nk) {
            LOAD_STAGE((i + 2) % 3, (i + 2) * BK);
            asm volatile("cp.async.wait_group 2;");
        } else if (i + 1 < nk) {
            asm volatile("cp.async.wait_group 1;");
        } else {
            asm volatile("cp.async.wait_group 0;");
        }
        __syncthreads();

        const float* Abase = As + s * STG + (wm * 32 + g) * PITCH;
        const float* Bbase = Bs + s * STG + (wn * 64 + g) * PITCH;
#pragma unroll
        for (int kk = 0; kk < 4; kk++) {
            const int k0 = kk * 8 + t4;
            uint32_t a[2][4], b[8][2];
#pragma unroll
            for (int t = 0; t < 2; t++) {
                const float* p = Abase + t * 16 * PITCH + k0;
                a[t][0] = FU(p[0]);
                a[t][1] = FU(p[8 * PITCH]);
                a[t][2] = FU(p[4]);
                a[t][3] = FU(p[8 * PITCH + 4]);
            }
#pragma unroll
            for (int n = 0; n < 8; n++) {
                const float* p = Bbase + n * 8 * PITCH + k0;
                b[n][0] = FU(p[0]);
                b[n][1] = FU(p[4]);
            }
#pragma unroll
            for (int t = 0; t < 2; t++)
#pragma unroll
                for (int n = 0; n < 8; n++)
                    MMA4(c[t][n], a[t][0], a[t][1], a[t][2], a[t][3], b[n][0], b[n][1]);
        }
        __syncthreads();
    }

    // epilogue: optional fused K-RoPE (mode 2) + tf32 rounding (mode >= 1)
#pragma unroll
    for (int t = 0; t < 2; t++) {
        const int row = m0 + wm * 32 + t * 16 + g;
#pragma unroll
        for (int n = 0; n < 8; n++) {
            const int col = n0 + wn * 64 + n * 8 + t4 * 2;
            float v0 = c[t][n][0], v1 = c[t][n][1];
            float v2 = c[t][n][2], v3 = c[t][n][3];
            if (mode == 2) {
                int ch = col & 127;
                if (ch < ROPE) {
                    int p = ch >> 1;
                    int s0 = row & (SS-1), s1 = (row + 8) & (SS-1);
                    float c0 = fcos[s0*32 + p], sn0 = fsin[s0*32 + p];
                    float c1 = fcos[s1*32 + p], sn1 = fsin[s1*32 + p];
                    float r0 = v0*c0 - v1*sn0, i0 = v0*sn0 + v1*c0;
                    float r1 = v2*c1 - v3*sn1, i1 = v2*sn1 + v3*c1;
                    v0 = r0; v1 = i0; v2 = r1; v3 = i1;
                }
            }
            if (mode >= 1) {
                v0 = rtf32f(v0); v1 = rtf32f(v1);
                v2 = rtf32f(v2); v3 = rtf32f(v3);
            }
            *(float2*)&C[(size_t)row * N + col]       = make_float2(v0, v1);
            *(float2*)&C[(size_t)(row + 8) * N + col] = make_float2(v2, v3);
        }
    }
}

// ---------------- tensor-core differential flash attention ---------------------
// (R10 measured-best version, unchanged)
#define QKP 272
#define VP  264
#define PP  36
#define SM_KS (64*QKP)
#define SM_VS (SM_KS + 64*QKP)
#define SM_PS (SM_VS + 64*VP)
#define SM_MS (SM_PS + 2*64*PP)
#define ATT_SMEM ((SM_MS + 3*128 + 4) * (int)sizeof(float))   // 226832 B

__global__ __launch_bounds__(512) void attn_mma(
    const float* __restrict__ rms_scale,
    const float* __restrict__ fcos, const float* __restrict__ fsin,
    const float* __restrict__ lq1, const float* __restrict__ lk1,
    const float* __restrict__ lq2, const float* __restrict__ lk2)
{
    extern __shared__ float smf[];
    float* Qs = smf;              // [64][272]
    float* Ks = smf + SM_KS;      // [2][32][272]
    float* Vs = smf + SM_VS;      // [2][32][264]
    float* Ps = smf + SM_PS;      // [2][64][36]
    float* ms = smf + SM_MS;
    float* ls = ms + 128;
    float* fs = ls + 128;
    float* lam_s = fs + 128;
    float* Osm = Ks;              // epilogue reuse: [64][272]

    const int qt   = 31 - blockIdx.x;
    const int bh   = blockIdx.y;
    const int b    = bh >> 4, h = bh & 15;
    const int tid  = threadIdx.x;
    const int wid  = tid >> 5;
    const int lane = tid & 31;
    const int g    = lane >> 2;
    const int t4   = lane & 3;
    const int qb   = qt * 64;

    const int s_qrg = wid & 3, s_br = (wid >> 2) & 1, s_kh = wid >> 3;
    const int p_vq = wid & 3, p_br = (wid >> 2) & 1, p_qrg = wid >> 3;

    const uint32_t ks_u = cvta_smem(Ks);
    const uint32_t vs_u = cvta_smem(Vs);

    const size_t qgbase = (size_t)(b*SS + qb) * INNER + h*HD2;
    const int nkt = 2*qt + 2;

#define ATT_PREFETCH(stg, kt_) do { \
    const size_t kb_ = (size_t)(b*SS + (kt_)*32) * INNER + h*HD2; \
    _Pragma("unroll") \
    for (int it = 0; it < 4; it++) { \
        int idx_ = tid + it*512; \
        int r_ = idx_ >> 6, c4_ = (idx_ & 63) << 2; \
        uint32_t offk = (uint32_t)(((stg)*32 + r_)*QKP + c4_) * 4; \
        uint32_t offv = (uint32_t)(((stg)*32 + r_)*VP + c4_) * 4; \
        asm volatile("cp.async.cg.shared.global [%0], [%1], 16;" \
                     :: "r"(ks_u + offk), "l"(&d_K[kb_ + (size_t)r_*INNER + c4_])); \
        asm volatile("cp.async.cg.shared.global [%0], [%1], 16;" \
                     :: "r"(vs_u + offv), "l"(&d_V[kb_ + (size_t)r_*INNER + c4_])); \
    } \
    asm volatile("cp.async.commit_group;"); \
} while (0)

    ATT_PREFETCH(0, 0);

    // Q tile load (64 x 256)
#pragma unroll
    for (int it = 0; it < 8; it++) {
        int idx = tid + it*512;
        int r = idx >> 6, c4 = (idx & 63) << 2;
        *(float4*)&Qs[r*QKP + c4] = *(const float4*)&d_Q[qgbase + (size_t)r*INNER + c4];
    }
    if (tid < 128) { ms[tid] = -1e30f; ls[tid] = 0.f; }
    if (wid == 0) {
        float s1 = 0.f, s2 = 0.f;
#pragma unroll
        for (int i = 0; i < 4; i++) {
            int idx = h*HD + lane*4 + i;
            s1 += lq1[idx]*lk1[idx];
            s2 += lq2[idx]*lk2[idx];
        }
#pragma unroll
        for (int o = 16; o; o >>= 1) {
            s1 += __shfl_xor_sync(0xffffffffu, s1, o);
            s2 += __shfl_xor_sync(0xffffffffu, s2, o);
        }
        if (lane == 0) lam_s[0] = __expf(s1) - __expf(s2) + LAMBDA_INIT;
    }
    __syncthreads();

    // fused RoPE on Q (rounded to tf32): dims 0..63 of each 128-half
#pragma unroll
    for (int it = 0; it < 8; it++) {
        int idx = tid + it*512;
        int r = idx >> 6, pp = idx & 63;
        int half = pp >> 5, p = pp & 31;
        float c  = fcos[(qb + r)*32 + p];
        float sn = fsin[(qb + r)*32 + p];
        float* x = &Qs[r*QKP + half*128 + 2*p];
        float xr = x[0], xi = x[1];
        x[0] = rtf32f(xr*c - xi*sn);
        x[1] = rtf32f(xr*sn + xi*c);
    }

    float oc[2][8][4];
#pragma unroll
    for (int t = 0; t < 2; t++)
#pragma unroll
        for (int n = 0; n < 8; n++)
#pragma unroll
            for (int j = 0; j < 4; j++) oc[t][n][j] = 0.f;

    for (int kt = 0; kt < nkt; kt++) {
        const int st = kt & 1;
        if (kt + 1 < nkt) {
            ATT_PREFETCH(st ^ 1, kt + 1);
            asm volatile("cp.async.wait_group 1;");
        } else {
            asm volatile("cp.async.wait_group 0;");
        }
        __syncthreads();

        // ---- scores: float4 frags, k-relabeled ----
        {
            float cs[2][4] = {{0,0,0,0},{0,0,0,0}};
            const float* Qb = Qs + (s_qrg*16 + g)*QKP + s_br*128 + 4*t4;
            const float* Kb = Ks + st*32*QKP + (s_kh*16 + g)*QKP + s_br*128 + 4*t4;
#pragma unroll
            for (int grp = 0; grp < 8; grp++) {
                float4 qa  = *(const float4*)(Qb + grp*16);
                float4 qb_ = *(const float4*)(Qb + 8*QKP + grp*16);
                float4 ka  = *(const float4*)(Kb + grp*16);
                float4 kb2 = *(const float4*)(Kb + 8*QKP + grp*16);
                MMA4(cs[0], FU(qa.x), FU(qb_.x), FU(qa.y), FU(qb_.y), FU(ka.x),  FU(ka.y));
                MMA4(cs[0], FU(qa.z), FU(qb_.z), FU(qa.w), FU(qb_.w), FU(ka.z),  FU(ka.w));
                MMA4(cs[1], FU(qa.x), FU(qb_.x), FU(qa.y), FU(qb_.y), FU(kb2.x), FU(kb2.y));
                MMA4(cs[1], FU(qa.z), FU(qb_.z), FU(qa.w), FU(qb_.w), FU(kb2.z), FU(kb2.w));
            }
            const int row0 = qb + s_qrg*16 + g;
#pragma unroll
            for (int nt = 0; nt < 2; nt++) {
                int coln = kt*32 + s_kh*16 + nt*8 + 2*t4;
                float* pp = Ps + (s_br*64 + s_qrg*16 + g)*PP + s_kh*16 + nt*8 + 2*t4;
                pp[0]      = (coln   <= row0)   ? cs[nt][0]*SCALE : -1e30f;
                pp[1]      = (coln+1 <= row0)   ? cs[nt][1]*SCALE : -1e30f;
                pp[8*PP]   = (coln   <= row0+8) ? cs[nt][2]*SCALE : -1e30f;
                pp[8*PP+1] = (coln+1 <= row0+8) ? cs[nt][3]*SCALE : -1e30f;
            }
        }
        __syncthreads();

        // ---- online softmax (each warp: 8 row-branches), P rounded to tf32 ----
#pragma unroll
        for (int j = 0; j < 8; j++) {
            int rb = wid*8 + j;
            int br = rb >> 6, row = rb & 63;
            float* pr = Ps + (br*64 + row)*PP;
            float v = pr[lane];
            float mx = v;
#pragma unroll
            for (int o = 16; o; o >>= 1) mx = fmaxf(mx, __shfl_xor_sync(0xffffffffu, mx, o));
            float mo = ms[br*64 + row];
            float mn = fmaxf(mo, mx);
            float p = (v > -1e29f) ? rtf32f(__expf(v - mn)) : 0.f;
            float su = p;
#pragma unroll
            for (int o = 16; o; o >>= 1) su += __shfl_xor_sync(0xffffffffu, su, o);
            pr[lane] = p;
            if (lane == 0) {
                float f = __expf(mo - mn);
                fs[br*64 + row] = f;
                ls[br*64 + row] = ls[br*64 + row]*f + su;
                ms[br*64 + row] = mn;
            }
        }
        __syncthreads();

        // ---- PV: O_br += P_br V (warp: 32q x 64v, kdim 32) ----
        {
            const int rbase = p_br*64 + p_qrg*32;
            float f0 = fs[rbase + g],       f1 = fs[rbase + g + 8];
            float f2_ = fs[rbase + 16 + g], f3_ = fs[rbase + 16 + g + 8];
#pragma unroll
            for (int nt = 0; nt < 8; nt++) {
                oc[0][nt][0] *= f0;  oc[0][nt][1] *= f0;
                oc[0][nt][2] *= f1;  oc[0][nt][3] *= f1;
                oc[1][nt][0] *= f2_; oc[1][nt][1] *= f2_;
                oc[1][nt][2] *= f3_; oc[1][nt][3] *= f3_;
            }
            const float* Pb = Ps + (p_br*64 + p_qrg*32 + g)*PP;
            const float* Vb = Vs + st*32*VP + p_vq*64;
#pragma unroll
            for (int ki = 0; ki < 4; ki++) {
                const int kc = ki*8 + t4;
                uint32_t pa[2][4];
#pragma unroll
                for (int t = 0; t < 2; t++) {
                    const float* pr = Pb + t*16*PP;
                    pa[t][0] = FU(pr[kc]);
                    pa[t][1] = FU(pr[8*PP + kc]);
                    pa[t][2] = FU(pr[kc+4]);
                    pa[t][3] = FU(pr[8*PP + kc+4]);
                }
                const float* v0p = Vb + kc*VP + g;
                const float* v1p = v0p + 4*VP;
#pragma unroll
                for (int nt = 0; nt < 8; nt++) {
                    uint32_t b0 = FU(v0p[nt*8]);
                    uint32_t b1 = FU(v1p[nt*8]);
                    MMA4(oc[0][nt], pa[0][0], pa[0][1], pa[0][2], pa[0][3], b0, b1);
                    MMA4(oc[1][nt], pa[1][0], pa[1][1], pa[1][2], pa[1][3], b0, b1);
                }
            }
        }
        __syncthreads();
    }

    // ---- epilogue: combine branches, RMS-norm, write d_O ----
    {
        const int rbase = p_qrg*32;
        const int lb = p_br*64 + rbase;
        float li0 = 1.f / ls[lb + g];
        float li1 = 1.f / ls[lb + g + 8];
        float li2 = 1.f / ls[lb + 16 + g];
        float li3 = 1.f / ls[lb + 16 + g + 8];

        if (p_br == 0) {
#pragma unroll
            for (int t = 0; t < 2; t++) {
                int r0 = rbase + t*16 + g;
                float la = t ? li2 : li0, lbv = t ? li3 : li1;
#pragma unroll
                for (int nt = 0; nt < 8; nt++) {
                    int col = p_vq*64 + nt*8 + 2*t4;
                    Osm[r0*QKP + col]       = oc[t][nt][0]*la;
                    Osm[r0*QKP + col + 1]   = oc[t][nt][1]*la;
                    Osm[(r0+8)*QKP + col]   = oc[t][nt][2]*lbv;
                    Osm[(r0+8)*QKP + col+1] = oc[t][nt][3]*lbv;
                }
            }
        }
        __syncthreads();
        if (p_br == 1) {
            const float lam = lam_s[0];
#pragma unroll
            for (int t = 0; t < 2; t++) {
                int r0 = rbase + t*16 + g;
                float la = t ? li2 : li0, lbv = t ? li3 : li1;
#pragma unroll
                for (int nt = 0; nt < 8; nt++) {
                    int col = p_vq*64 + nt*8 + 2*t4;
                    Osm[r0*QKP + col]       -= lam*oc[t][nt][0]*la;
                    Osm[r0*QKP + col + 1]   -= lam*oc[t][nt][1]*la;
                    Osm[(r0+8)*QKP + col]   -= lam*oc[t][nt][2]*lbv;
                    Osm[(r0+8)*QKP + col+1] -= lam*oc[t][nt][3]*lbv;
                }
            }
        }
        __syncthreads();

#pragma unroll
        for (int j = 0; j < 4; j++) {
            int row = wid*4 + j;
            float vals[8];
            float ssq = 0.f;
#pragma unroll
            for (int i = 0; i < 8; i++) {
                float v = Osm[row*QKP + lane + 32*i];
                vals[i] = v;
                ssq += v*v;
            }
#pragma unroll
            for (int o = 16; o; o >>= 1) ssq += __shfl_xor_sync(0xffffffffu, ssq, o);
            float rn = rsqrtf(ssq * (1.f/256.f) + EPSV) * (1.f - LAMBDA_INIT);
            size_t gb = (size_t)(b*SS + qb + row) * INNER + h*HD2;
#pragma unroll
            for (int i = 0; i < 8; i++) {
                int col = lane + 32*i;
                d_O[gb + col] = vals[i] * rn * rms_scale[h*HD2 + col];
            }
        }
    }
}

// ---------------- launch --------------------------------------------------------
extern "C" void kernel_launch(void* const* d_in, const int* in_sizes, int n_in,
                              void* d_out, int out_size)
{
    const float* x    = (const float*)d_in[0];
    const float* w_q  = (const float*)d_in[1];
    const float* w_k  = (const float*)d_in[2];
    const float* w_v  = (const float*)d_in[3];
    const float* w_o  = (const float*)d_in[4];
    const float* lq1  = (const float*)d_in[5];
    const float* lk1  = (const float*)d_in[6];
    const float* lq2  = (const float*)d_in[7];
    const float* lk2  = (const float*)d_in[8];
    const float* rsc  = (const float*)d_in[9];
    const float* fcos = (const float*)d_in[10];
    const float* fsin = (const float*)d_in[11];
    float* out = (float*)d_out;

    float *Q, *K, *V, *O, *Xr, *Wqr, *Wkr, *Wvr, *Wor;
    cudaGetSymbolAddress((void**)&Q,   d_Q);
    cudaGetSymbolAddress((void**)&K,   d_K);
    cudaGetSymbolAddress((void**)&V,   d_V);
    cudaGetSymbolAddress((void**)&O,   d_O);
    cudaGetSymbolAddress((void**)&Xr,  d_Xr);
    cudaGetSymbolAddress((void**)&Wqr, d_Wqr);
    cudaGetSymbolAddress((void**)&Wkr, d_Wkr);
    cudaGetSymbolAddress((void**)&Wvr, d_Wvr);
    cudaGetSymbolAddress((void**)&Wor, d_Wor);

    cudaFuncSetAttribute(gemm_mma, cudaFuncAttributeMaxDynamicSharedMemorySize, GEMM_SMEM);
    cudaFuncSetAttribute(attn_mma, cudaFuncAttributeMaxDynamicSharedMemorySize, ATT_SMEM);

    const int n4 = (MS * DIM) / 4;   // 2M float4 per 4096x2048 matrix
    round_tf32_kernel<<<n4/256, 256>>>((const float4*)x,   (float4*)Xr,  n4);  // idx 0
    round_tf32_kernel<<<n4/256, 256>>>((const float4*)w_q, (float4*)Wqr, n4);  // idx 1
    round_tf32_kernel<<<n4/256, 256>>>((const float4*)w_k, (float4*)Wkr, n4);  // idx 2

    dim3 gq(INNER/BN, MS/BM);
    gemm_mma<<<gq, 256, GEMM_SMEM>>>(Xr, Wqr, Q, MS, INNER, DIM, 1, nullptr, nullptr); // idx 3 (profiled)
    gemm_mma<<<gq, 256, GEMM_SMEM>>>(Xr, Wkr, K, MS, INNER, DIM, 2, fcos, fsin);       // idx 4: +RoPE

    round_tf32_kernel<<<n4/256, 256>>>((const float4*)w_v, (float4*)Wvr, n4);          // idx 5
    gemm_mma<<<gq, 256, GEMM_SMEM>>>(Xr, Wvr, V, MS, INNER, DIM, 1, nullptr, nullptr); // idx 6
    round_tf32_kernel<<<n4/256, 256>>>((const float4*)w_o, (float4*)Wor, n4);          // idx 7

    attn_mma<<<dim3(SS/64, BB*NH), 512, ATT_SMEM>>>(rsc, fcos, fsin, lq1, lk1, lq2, lk2); // idx 8

    dim3 go(DIM/BN, MS/BM);
    gemm_mma<<<go, 256, GEMM_SMEM>>>(O, Wor, out, MS, DIM, INNER, 0, nullptr, nullptr);   // idx 9
}